// round 7
// baseline (speedup 1.0000x reference)
#include <cuda_runtime.h>
#include <cstdint>
#include <math.h>

#define EN_MAX 200000
#define TN_MAX 600000
#define HH 128
#define IC 64
#define BSZ 8
#define NRAD 6
#define SBFK 42
#define TK 294

typedef unsigned long long ull;

// ---------------- scratch (device globals; no allocations) ----------------
__device__ float g_xji[EN_MAX * HH];
__device__ float g_rbfh[EN_MAX * HH];
__device__ float g_rbfh2[EN_MAX * HH];
__device__ float g_rb8[EN_MAX * BSZ];
__device__ float g_xdown[EN_MAX * IC];
__device__ float g_acc[EN_MAX * IC];
__device__ float g_t8[TN_MAX * BSZ];
__device__ float g_s8[TN_MAX * BSZ];
__device__ float g_bufA[EN_MAX * HH];
__device__ float g_bufB[EN_MAX * HH];
__device__ float g_bufC[EN_MAX * HH];

__device__ __forceinline__ float silu_f(float x) {
    return x / (1.0f + __expf(-x));
}

// packed f32x2 FMA (ptxas never auto-fuses; PTX only)
__device__ __forceinline__ void ffma2(ull& c, ull a, ull b) {
    asm("fma.rn.f32x2 %0, %1, %2, %0;" : "+l"(c) : "l"(a), "l"(b));
}
__device__ __forceinline__ void unpack2(ull v, float& lo, float& hi) {
    unsigned int a, b;
    asm("mov.b64 {%0, %1}, %2;" : "=r"(a), "=r"(b) : "l"(v));
    lo = __uint_as_float(a);
    hi = __uint_as_float(b);
}

// ---------------- FFMA2 register-tiled GEMM, zero-mov inner loop ----------
// out[row, j] = epi( sum_k in[row,k] * W[k,j] )
// CTA: 128 x NOUT tile, 256 threads, thread tile 8 rows x TC cols held as
// 4 row-pair f32x2 accumulators x TC. A staged k-major (row-pairs pack
// naturally); B staged pre-DUPLICATED as u64 {b,b}. Inner loop: LDS only.
template <int KIN, int NOUT>
__global__ void __launch_bounds__(256, 2)
gemm_f2(const float* __restrict__ in,
        const float* __restrict__ W,
        const float* __restrict__ bias,
        const float* __restrict__ mulv,
        const float* __restrict__ addv,
        float* __restrict__ out,
        const float* __restrict__ mul2,
        float* __restrict__ out2,
        int nrows, int act)
{
    constexpr int KB = 32;                 // k-chunk
    constexpr int NC = KIN / KB;           // 4 or 2
    constexpr int APITCH = 132;            // floats per k-row (528B, 16B mult)
    constexpr int TC = NOUT / 16;          // cols per thread (8 or 4)

    extern __shared__ char smem[];
    float* As = reinterpret_cast<float*>(smem);                       // [KB][APITCH]
    ull*   Bs = reinterpret_cast<ull*>(smem + KB * APITCH * 4);       // [KB][NOUT] dup'd

    const int tid = threadIdx.x;
    const int tr = tid >> 4;               // row group 0..15 (8 rows each)
    const int tc = tid & 15;               // col group 0..15 (TC cols each)
    const int r0 = blockIdx.x * 128;

    ull acc[4][TC];
    #pragma unroll
    for (int p = 0; p < 4; ++p)
        #pragma unroll
        for (int j = 0; j < TC; ++j) acc[p][j] = 0ull;

    for (int c = 0; c < NC; ++c) {
        if (c) __syncthreads();
        // ---- stage A chunk transposed (k-major) ----
        {
            const int row = tid >> 1, part = tid & 1;
            int gr = r0 + row;
            if (gr >= nrows) gr = nrows - 1;
            const float* src = in + (size_t)gr * KIN + c * KB + part * 16;
            #pragma unroll
            for (int f = 0; f < 4; ++f) {
                const float4 v = *reinterpret_cast<const float4*>(src + f * 4);
                const int kk = part * 16 + f * 4;
                As[(kk + 0) * APITCH + row] = v.x;
                As[(kk + 1) * APITCH + row] = v.y;
                As[(kk + 2) * APITCH + row] = v.z;
                As[(kk + 3) * APITCH + row] = v.w;
            }
        }
        // ---- stage B chunk duplicated: Bs[k][j] = {W[k][j], W[k][j]} ----
        {
            #pragma unroll
            for (int t = tid; t < KB * NOUT / 4; t += 256) {
                const int k = t / (NOUT / 4), j4 = t % (NOUT / 4);
                const float4 v = *reinterpret_cast<const float4*>(
                    W + (size_t)(c * KB + k) * NOUT + j4 * 4);
                const uint32_t bx = __float_as_uint(v.x), by = __float_as_uint(v.y);
                const uint32_t bz = __float_as_uint(v.z), bw = __float_as_uint(v.w);
                uint4* dst = reinterpret_cast<uint4*>(Bs + (size_t)k * NOUT + j4 * 4);
                dst[0] = make_uint4(bx, bx, by, by);
                dst[1] = make_uint4(bz, bz, bw, bw);
            }
        }
        __syncthreads();

        #pragma unroll
        for (int k = 0; k < KB; ++k) {
            const ulonglong2* ap = reinterpret_cast<const ulonglong2*>(As + k * APITCH + tr * 8);
            const ulonglong2 a01 = ap[0], a23 = ap[1];
            const ull a[4] = {a01.x, a01.y, a23.x, a23.y};
            const ulonglong2* bp = reinterpret_cast<const ulonglong2*>(Bs + (size_t)k * NOUT + tc * TC);
            ull b[TC];
            #pragma unroll
            for (int h = 0; h < TC / 2; ++h) {
                const ulonglong2 bb = bp[h];
                b[2 * h] = bb.x; b[2 * h + 1] = bb.y;
            }
            #pragma unroll
            for (int p = 0; p < 4; ++p)
                #pragma unroll
                for (int j = 0; j < TC; ++j)
                    ffma2(acc[p][j], a[p], b[j]);
        }
    }

    // ---- epilogue: each acc pair = rows (tr*8+2p, tr*8+2p+1), cols tc*TC.. ----
    float bv[TC];
    #pragma unroll
    for (int j = 0; j < TC; ++j) bv[j] = bias ? bias[tc * TC + j] : 0.f;

    #pragma unroll
    for (int p = 0; p < 4; ++p) {
        float ve[TC], vo[TC];
        #pragma unroll
        for (int j = 0; j < TC; ++j) unpack2(acc[p][j], ve[j], vo[j]);
        #pragma unroll
        for (int half = 0; half < 2; ++half) {
            float* v = half ? vo : ve;
            const int row = r0 + tr * 8 + 2 * p + half;
            if (row >= nrows) continue;
            const size_t o = (size_t)row * NOUT + tc * TC;
            #pragma unroll
            for (int j = 0; j < TC; ++j) {
                float x = v[j] + bv[j];
                if (act) x = silu_f(x);
                v[j] = x;
            }
            if (mulv) {
                #pragma unroll
                for (int j = 0; j < TC; ++j) v[j] *= mulv[o + j];
            }
            if (addv) {
                #pragma unroll
                for (int j = 0; j < TC; ++j) v[j] += addv[o + j];
            }
            #pragma unroll
            for (int j4 = 0; j4 < TC / 4; ++j4)
                *reinterpret_cast<float4*>(out + o + j4 * 4) =
                    make_float4(v[j4 * 4], v[j4 * 4 + 1], v[j4 * 4 + 2], v[j4 * 4 + 3]);
            if (out2) {
                #pragma unroll
                for (int j4 = 0; j4 < TC / 4; ++j4) {
                    const float4 m = *reinterpret_cast<const float4*>(mul2 + o + j4 * 4);
                    *reinterpret_cast<float4*>(out2 + o + j4 * 4) =
                        make_float4(v[j4 * 4] * m.x, v[j4 * 4 + 1] * m.y,
                                    v[j4 * 4 + 2] * m.z, v[j4 * 4 + 3] * m.w);
                }
            }
        }
    }
}

// ---------------- rbf basis helpers ----------------
__global__ void rb8_kernel(const float* __restrict__ rbf, const float* __restrict__ W1,
                           float* __restrict__ out, int n)
{
    const int e = blockIdx.x * blockDim.x + threadIdx.x;
    if (e >= n) return;
    float r[NRAD];
    #pragma unroll
    for (int i = 0; i < NRAD; ++i) r[i] = rbf[(size_t)e * NRAD + i];
    #pragma unroll
    for (int b = 0; b < BSZ; ++b) {
        float s = 0.f;
        #pragma unroll
        for (int i = 0; i < NRAD; ++i) s += r[i] * __ldg(&W1[i * BSZ + b]);
        out[(size_t)e * BSZ + b] = s;
    }
}

__global__ void rbfh_kernel(const float* __restrict__ rb8, const float* __restrict__ rbf,
                            const float* __restrict__ W_rbf2, const float* __restrict__ W_rbf,
                            float* __restrict__ rbfh, float* __restrict__ rbfh2, int n)
{
    __shared__ float w2[BSZ * HH];
    __shared__ float wr[NRAD * HH];
    const int j = threadIdx.x;
    #pragma unroll
    for (int b = 0; b < BSZ; ++b) w2[b * HH + j] = W_rbf2[b * HH + j];
    #pragma unroll
    for (int r = 0; r < NRAD; ++r) wr[r * HH + j] = W_rbf[r * HH + j];
    __syncthreads();

    const int row0 = blockIdx.x * 32;
    for (int rr = 0; rr < 32; ++rr) {
        const int row = row0 + rr;
        if (row >= n) return;
        const float4* rp = reinterpret_cast<const float4*>(rb8 + (size_t)row * BSZ);
        const float4 ra = __ldg(rp), rb = __ldg(rp + 1);
        float a1 = ra.x * w2[0 * HH + j] + ra.y * w2[1 * HH + j] +
                   ra.z * w2[2 * HH + j] + ra.w * w2[3 * HH + j] +
                   rb.x * w2[4 * HH + j] + rb.y * w2[5 * HH + j] +
                   rb.z * w2[6 * HH + j] + rb.w * w2[7 * HH + j];
        float a2 = 0.f;
        #pragma unroll
        for (int r = 0; r < NRAD; ++r) a2 += __ldg(&rbf[(size_t)row * NRAD + r]) * wr[r * HH + j];
        rbfh[(size_t)row * HH + j]  = a1;
        rbfh2[(size_t)row * HH + j] = a2;
    }
}

// ---------------- T-space: X[T,K] @ W1[K,8] -> out8[T,8] ----------------
template <int K, int PK>
__global__ void proj8_kernel(const float* __restrict__ X, const float* __restrict__ W1,
                             float* __restrict__ out8, int nrows)
{
    __shared__ float wcm[BSZ * PK];
    __shared__ float red[8][32 * 33];
    const int tid = threadIdx.x;
    for (int x = tid; x < BSZ * PK; x += blockDim.x) wcm[x] = 0.f;
    __syncthreads();
    for (int x = tid; x < K * BSZ; x += blockDim.x) {
        const int i = x / BSZ, b = x % BSZ;
        wcm[b * PK + i] = W1[x];
    }
    __syncthreads();

    const int warp = tid >> 5, lane = tid & 31;
    float* myred = &red[warp][0];
    const int nw = blockDim.x >> 5;
    constexpr int ITERS = (K + 31) / 32;

    for (int r0 = (blockIdx.x * nw + warp) * 4; r0 < nrows; r0 += gridDim.x * nw * 4) {
        float acc[4][BSZ] = {};
        const float* x0 = X + (size_t)r0 * K;
        #pragma unroll
        for (int k = 0; k < ITERS; ++k) {
            const int i = lane + k * 32;
            float xv[4] = {0.f, 0.f, 0.f, 0.f};
            if (i < K) {
                #pragma unroll
                for (int rr = 0; rr < 4; ++rr) xv[rr] = x0[(size_t)rr * K + i];
            }
            #pragma unroll
            for (int b = 0; b < BSZ; ++b) {
                const float w = wcm[b * PK + i];
                #pragma unroll
                for (int rr = 0; rr < 4; ++rr) acc[rr][b] += w * xv[rr];
            }
        }
        #pragma unroll
        for (int rr = 0; rr < 4; ++rr)
            #pragma unroll
            for (int b = 0; b < BSZ; ++b)
                myred[lane * 33 + rr * BSZ + b] = acc[rr][b];
        __syncwarp();
        float s = 0.f;
        #pragma unroll
        for (int l = 0; l < 32; ++l) s += myred[l * 33 + lane];
        out8[(size_t)r0 * BSZ + lane] = s;
        __syncwarp();
    }
}

// ---------------- triplet gather/scale/scatter ----------------
__global__ void triplet_kernel(const float* __restrict__ t8, const float* __restrict__ s8,
                               const float* __restrict__ W_t2, const float* __restrict__ W_sbf2,
                               const float* __restrict__ xdown,
                               const int* __restrict__ idx_kj, const int* __restrict__ idx_ji,
                               float* __restrict__ acc, int nt)
{
    __shared__ float wt2s[BSZ * IC];
    __shared__ float ws2s[BSZ * IC];
    const int tid = threadIdx.x;
    for (int i = tid; i < BSZ * IC; i += blockDim.x) { wt2s[i] = W_t2[i]; ws2s[i] = W_sbf2[i]; }
    __syncthreads();

    const int warp = tid >> 5, lane = tid & 31;
    const int total_warps = (blockDim.x * gridDim.x) >> 5;

    for (int tr = blockIdx.x * (blockDim.x >> 5) + warp; tr < nt; tr += total_warps) {
        const float4* tp = reinterpret_cast<const float4*>(t8 + (size_t)tr * BSZ);
        const float4 ta = __ldg(tp), tb = __ldg(tp + 1);
        const float4* sp = reinterpret_cast<const float4*>(s8 + (size_t)tr * BSZ);
        const float4 sa = __ldg(sp), sb = __ldg(sp + 1);
        const float tv[BSZ] = {ta.x, ta.y, ta.z, ta.w, tb.x, tb.y, tb.z, tb.w};
        const float sv[BSZ] = {sa.x, sa.y, sa.z, sa.w, sb.x, sb.y, sb.z, sb.w};
        const int kj = idx_kj[tr], ji = idx_ji[tr];
        const int c0 = lane, c1 = lane + 32;
        float t0 = 0.f, t1 = 0.f, s0 = 0.f, s1 = 0.f;
        #pragma unroll
        for (int b = 0; b < BSZ; ++b) {
            t0 += tv[b] * wt2s[b * IC + c0];
            t1 += tv[b] * wt2s[b * IC + c1];
            s0 += sv[b] * ws2s[b * IC + c0];
            s1 += sv[b] * ws2s[b * IC + c1];
        }
        const float g0 = xdown[(size_t)kj * IC + c0];
        const float g1 = xdown[(size_t)kj * IC + c1];
        atomicAdd(acc + (size_t)ji * IC + c0, g0 * t0 * s0);
        atomicAdd(acc + (size_t)ji * IC + c1, g1 * t1 * s1);
    }
}

__global__ void zero4_kernel(float4* __restrict__ p, int n4)
{
    const int i = blockIdx.x * blockDim.x + threadIdx.x;
    if (i < n4) p[i] = make_float4(0.f, 0.f, 0.f, 0.f);
}

// ---------------- launch ----------------
extern "C" void kernel_launch(void* const* d_in, const int* in_sizes, int n_in,
                              void* d_out, int out_size)
{
    const float* e1     = (const float*)d_in[0];
    const float* rbf    = (const float*)d_in[1];
    const float* sbf    = (const float*)d_in[2];
    const float* tt     = (const float*)d_in[3];
    const int*   idx_kj = (const int*)d_in[4];
    const int*   idx_ji = (const int*)d_in[5];
    const float* W_rbf1 = (const float*)d_in[6];
    const float* W_rbf2 = (const float*)d_in[7];
    const float* W_sbf1 = (const float*)d_in[8];
    const float* W_sbf2 = (const float*)d_in[9];
    const float* W_t1   = (const float*)d_in[10];
    const float* W_t2   = (const float*)d_in[11];
    const float* W_rbf  = (const float*)d_in[12];
    const float* W_kj   = (const float*)d_in[13];
    const float* b_kj   = (const float*)d_in[14];
    const float* W_ji   = (const float*)d_in[15];
    const float* b_ji   = (const float*)d_in[16];
    const float* W_down = (const float*)d_in[17];
    const float* W_up   = (const float*)d_in[18];
    const float* Wb1    = (const float*)d_in[19];
    const float* bb1    = (const float*)d_in[20];
    const float* Wb2    = (const float*)d_in[21];
    const float* bb2    = (const float*)d_in[22];
    const float* W_lin  = (const float*)d_in[23];
    const float* b_lin  = (const float*)d_in[24];
    const float* Wa1    = (const float*)d_in[25];
    const float* ba1    = (const float*)d_in[26];
    const float* Wa2    = (const float*)d_in[27];
    const float* ba2    = (const float*)d_in[28];

    const int E = in_sizes[0] / HH;
    const int T = in_sizes[4];

    float *xji, *rbfh, *rbfh2, *rb8, *xdown, *acc, *t8, *s8, *A, *B, *C;
    cudaGetSymbolAddress((void**)&xji,   g_xji);
    cudaGetSymbolAddress((void**)&rbfh,  g_rbfh);
    cudaGetSymbolAddress((void**)&rbfh2, g_rbfh2);
    cudaGetSymbolAddress((void**)&rb8,   g_rb8);
    cudaGetSymbolAddress((void**)&xdown, g_xdown);
    cudaGetSymbolAddress((void**)&acc,   g_acc);
    cudaGetSymbolAddress((void**)&t8,    g_t8);
    cudaGetSymbolAddress((void**)&s8,    g_s8);
    cudaGetSymbolAddress((void**)&A,     g_bufA);
    cudaGetSymbolAddress((void**)&B,     g_bufB);
    cudaGetSymbolAddress((void**)&C,     g_bufC);

    float* out_e1 = (float*)d_out;
    float* out_e2 = (float*)d_out + (size_t)E * HH;

    const int WS = HH * HH;

    // dynamic smem: As[32][132]*4B + Bs[32][NOUT]*8B
    const int sm_hh = 32 * 132 * 4 + 32 * 128 * 8;   // 49664
    const int sm_dn = 32 * 132 * 4 + 32 * 64 * 8;    // 33280
    const int sm_up = 32 * 132 * 4 + 32 * 128 * 8;   // 49664
    cudaFuncSetAttribute(gemm_f2<HH, HH>, cudaFuncAttributeMaxDynamicSharedMemorySize, sm_hh);
    cudaFuncSetAttribute(gemm_f2<HH, IC>, cudaFuncAttributeMaxDynamicSharedMemorySize, sm_dn);
    cudaFuncSetAttribute(gemm_f2<IC, HH>, cudaFuncAttributeMaxDynamicSharedMemorySize, sm_up);

    const int gblocks = (E + 127) / 128;

    // stream index 3 = profiled launch (harness offset +2): gemm_f2<128,128>
    rb8_kernel<<<(E + 255) / 256, 256>>>(rbf, W_rbf1, rb8, E);                       // 0
    rbfh_kernel<<<(E + 31) / 32, HH>>>(rb8, rbf, W_rbf2, W_rbf, rbfh, rbfh2, E);     // 1
    zero4_kernel<<<(E * IC / 4 + 255) / 256, 256>>>((float4*)acc, E * IC / 4);       // 2

    // 3 (profiled): x_ji = silu(e1 @ W_ji + b_ji)
    gemm_f2<HH, HH><<<gblocks, 256, sm_hh>>>(e1, W_ji, b_ji, nullptr, nullptr, xji, nullptr, nullptr, E, 1);
    // A = silu(e1 @ W_kj + b_kj) * rbfh
    gemm_f2<HH, HH><<<gblocks, 256, sm_hh>>>(e1, W_kj, b_kj, rbfh, nullptr, A, nullptr, nullptr, E, 1);
    // xdown = silu(A @ W_down)
    gemm_f2<HH, IC><<<gblocks, 256, sm_dn>>>(A, W_down, nullptr, nullptr, nullptr, xdown, nullptr, nullptr, E, 1);

    // T-space projections
    proj8_kernel<TK, 320><<<2048, 256>>>(tt, W_t1, t8, T);
    proj8_kernel<SBFK, 64><<<2048, 256>>>(sbf, W_sbf1, s8, T);

    // gather * sbf_h * t_h, scatter-add by idx_ji
    triplet_kernel<<<2368, 256>>>(t8, s8, W_t2, W_sbf2, xdown, idx_kj, idx_ji, acc, T);

    // A = silu(acc @ W_up) + x_ji
    gemm_f2<IC, HH><<<gblocks, 256, sm_up>>>(acc, W_up, nullptr, nullptr, xji, A, nullptr, nullptr, E, 1);

    // residual before (1 layer)
    gemm_f2<HH, HH><<<gblocks, 256, sm_hh>>>(A, Wb1, bb1, nullptr, nullptr, B, nullptr, nullptr, E, 1);
    gemm_f2<HH, HH><<<gblocks, 256, sm_hh>>>(B, Wb2, bb2, nullptr, A, C, nullptr, nullptr, E, 1);

    // h = silu(C @ W_lin + b_lin) + e1
    gemm_f2<HH, HH><<<gblocks, 256, sm_hh>>>(C, W_lin, b_lin, nullptr, e1, A, nullptr, nullptr, E, 1);

    // residual after layer 0
    gemm_f2<HH, HH><<<gblocks, 256, sm_hh>>>(A, Wa1, ba1, nullptr, nullptr, B, nullptr, nullptr, E, 1);
    gemm_f2<HH, HH><<<gblocks, 256, sm_hh>>>(B, Wa2, ba2, nullptr, A, C, nullptr, nullptr, E, 1);
    // residual after layer 1 -> final outputs (e1_out, e2_out = e1_out * rbfh2)
    gemm_f2<HH, HH><<<gblocks, 256, sm_hh>>>(C, Wa1 + WS, ba1 + HH, nullptr, nullptr, B, nullptr, nullptr, E, 1);
    gemm_f2<HH, HH><<<gblocks, 256, sm_hh>>>(B, Wa2 + WS, ba2 + HH, nullptr, C, out_e1, rbfh2, out_e2, E, 1);
}

// round 8
// speedup vs baseline: 1.6753x; 1.6753x over previous
#include <cuda_runtime.h>
#include <cstdint>
#include <math.h>

#define EN_MAX 200000
#define TN_MAX 600000
#define HH 128
#define IC 64
#define BSZ 8
#define NRAD 6
#define SBFK 42
#define TK 294

typedef unsigned long long ull;

// ---------------- scratch (device globals; no allocations) ----------------
__device__ float g_xji[EN_MAX * HH];
__device__ float g_rbfh[EN_MAX * HH];
__device__ float g_rbfh2[EN_MAX * HH];
__device__ float g_rb8[EN_MAX * BSZ];
__device__ float g_xdown[EN_MAX * IC];
__device__ float g_acc[EN_MAX * IC];
__device__ float g_t8[TN_MAX * BSZ];
__device__ float g_s8[TN_MAX * BSZ];
__device__ float g_bufA[EN_MAX * HH];
__device__ float g_bufB[EN_MAX * HH];
__device__ float g_bufC[EN_MAX * HH];

__device__ __forceinline__ float silu_f(float x) {
    return x / (1.0f + __expf(-x));
}

// packed f32x2 FMA (ptxas never auto-fuses; PTX only)
__device__ __forceinline__ void ffma2(ull& c, ull a, ull b) {
    asm("fma.rn.f32x2 %0, %1, %2, %0;" : "+l"(c) : "l"(a), "l"(b));
}
__device__ __forceinline__ void unpack2(ull v, float& lo, float& hi) {
    unsigned int a, b;
    asm("mov.b64 {%0, %1}, %2;" : "=r"(a), "=r"(b) : "l"(v));
    lo = __uint_as_float(a);
    hi = __uint_as_float(b);
}

// ---------------- FFMA2 GEMM: zero-mov, conflict-free LDS ----------------
// out[row, j] = epi( sum_k in[row,k] * W[k,j] )
// CTA 128 x NOUT, 256 threads. Thread tile: 8 rows (4 f32x2 row-pairs) x
// (NOUT/16) cols. Column ownership strided: thread tc owns pairs
// P = tc + 16q (cols 2tc+32q, 2tc+32q+1) -> B LDS.128 at 16B lane stride
// (conflict-free). A k-major: row-pairs pack naturally (broadcast loads).
// B pre-duplicated {b,b} in smem, staged one uint4 per (k,pair).
template <int KIN, int NOUT>
__global__ void __launch_bounds__(256, 2)
gemm_f2(const float* __restrict__ in,
        const float* __restrict__ W,
        const float* __restrict__ bias,
        const float* __restrict__ mulv,
        const float* __restrict__ addv,
        float* __restrict__ out,
        const float* __restrict__ mul2,
        float* __restrict__ out2,
        int nrows, int act)
{
    constexpr int KB = 64;                 // k-chunk
    constexpr int NC = KIN / KB;           // 2 or 1
    constexpr int APITCH = 132;            // floats per k-row
    constexpr int NQ = NOUT / 32;          // B LDS.128 per thread (4 or 2)
    constexpr int NPAIR = NOUT / 2;        // column pairs per k-row

    extern __shared__ char smem[];
    float* As = reinterpret_cast<float*>(smem);                    // [KB][APITCH]
    ull*   Bs = reinterpret_cast<ull*>(smem + KB * APITCH * 4);    // [KB][NOUT] dup

    const int tid = threadIdx.x;
    const int tr = tid >> 4;               // row group 0..15 (8 rows)
    const int tc = tid & 15;               // col lane 0..15
    const int r0 = blockIdx.x * 128;

    ull acc[4][NQ][2];
    #pragma unroll
    for (int p = 0; p < 4; ++p)
        #pragma unroll
        for (int q = 0; q < NQ; ++q) { acc[p][q][0] = 0ull; acc[p][q][1] = 0ull; }

    for (int c = 0; c < NC; ++c) {
        if (c) __syncthreads();
        // ---- stage A chunk transposed (k-major) ----
        {
            const int row = tid >> 1, part = tid & 1;
            int gr = r0 + row;
            if (gr >= nrows) gr = nrows - 1;
            const float* src = in + (size_t)gr * KIN + c * KB + part * 32;
            #pragma unroll
            for (int f = 0; f < 8; ++f) {
                const float4 v = *reinterpret_cast<const float4*>(src + f * 4);
                const int kk = part * 32 + f * 4;
                As[(kk + 0) * APITCH + row] = v.x;
                As[(kk + 1) * APITCH + row] = v.y;
                As[(kk + 2) * APITCH + row] = v.z;
                As[(kk + 3) * APITCH + row] = v.w;
            }
        }
        // ---- stage B chunk: one uint4 {b0,b0,b1,b1} per (k, pair) ----
        {
            #pragma unroll
            for (int t = tid; t < KB * NPAIR; t += 256) {
                const int k = t / NPAIR, P = t % NPAIR;
                const float2 w = *reinterpret_cast<const float2*>(
                    W + (size_t)(c * KB + k) * NOUT + 2 * P);
                const uint32_t bx = __float_as_uint(w.x), by = __float_as_uint(w.y);
                *reinterpret_cast<uint4*>(Bs + (size_t)k * NOUT + 2 * P) =
                    make_uint4(bx, bx, by, by);
            }
        }
        __syncthreads();

        #pragma unroll 8
        for (int k = 0; k < KB; ++k) {
            const ulonglong2* ap = reinterpret_cast<const ulonglong2*>(As + k * APITCH + tr * 8);
            const ulonglong2 a01 = ap[0], a23 = ap[1];
            const ull a[4] = {a01.x, a01.y, a23.x, a23.y};
            const ull* bk = Bs + (size_t)k * NOUT;
            #pragma unroll
            for (int q = 0; q < NQ; ++q) {
                const ulonglong2 b = *reinterpret_cast<const ulonglong2*>(bk + q * 32 + tc * 2);
                #pragma unroll
                for (int p = 0; p < 4; ++p) {
                    ffma2(acc[p][q][0], a[p], b.x);
                    ffma2(acc[p][q][1], a[p], b.y);
                }
            }
        }
    }

    // ---- epilogue: pair p = rows tr*8+2p(+1); q -> cols 2tc+32q(+1) ----
    float bv[NQ][2];
    #pragma unroll
    for (int q = 0; q < NQ; ++q) {
        const int col = 2 * tc + 32 * q;
        bv[q][0] = bias ? bias[col] : 0.f;
        bv[q][1] = bias ? bias[col + 1] : 0.f;
    }

    #pragma unroll
    for (int p = 0; p < 4; ++p) {
        float ve[NQ][2], vo[NQ][2];
        #pragma unroll
        for (int q = 0; q < NQ; ++q) {
            unpack2(acc[p][q][0], ve[q][0], vo[q][0]);
            unpack2(acc[p][q][1], ve[q][1], vo[q][1]);
        }
        #pragma unroll
        for (int half = 0; half < 2; ++half) {
            const int row = r0 + tr * 8 + 2 * p + half;
            if (row >= nrows) continue;
            #pragma unroll
            for (int q = 0; q < NQ; ++q) {
                const int col = 2 * tc + 32 * q;
                const size_t o = (size_t)row * NOUT + col;
                float v0 = (half ? vo : ve)[q][0] + bv[q][0];
                float v1 = (half ? vo : ve)[q][1] + bv[q][1];
                if (act) { v0 = silu_f(v0); v1 = silu_f(v1); }
                if (mulv) {
                    const float2 m = *reinterpret_cast<const float2*>(mulv + o);
                    v0 *= m.x; v1 *= m.y;
                }
                if (addv) {
                    const float2 s = *reinterpret_cast<const float2*>(addv + o);
                    v0 += s.x; v1 += s.y;
                }
                *reinterpret_cast<float2*>(out + o) = make_float2(v0, v1);
                if (out2) {
                    const float2 m = *reinterpret_cast<const float2*>(mul2 + o);
                    *reinterpret_cast<float2*>(out2 + o) = make_float2(v0 * m.x, v1 * m.y);
                }
            }
        }
    }
}

// ---------------- rbf basis helpers ----------------
__global__ void rb8_kernel(const float* __restrict__ rbf, const float* __restrict__ W1,
                           float* __restrict__ out, int n)
{
    const int e = blockIdx.x * blockDim.x + threadIdx.x;
    if (e >= n) return;
    float r[NRAD];
    #pragma unroll
    for (int i = 0; i < NRAD; ++i) r[i] = rbf[(size_t)e * NRAD + i];
    #pragma unroll
    for (int b = 0; b < BSZ; ++b) {
        float s = 0.f;
        #pragma unroll
        for (int i = 0; i < NRAD; ++i) s += r[i] * __ldg(&W1[i * BSZ + b]);
        out[(size_t)e * BSZ + b] = s;
    }
}

__global__ void rbfh_kernel(const float* __restrict__ rb8, const float* __restrict__ rbf,
                            const float* __restrict__ W_rbf2, const float* __restrict__ W_rbf,
                            float* __restrict__ rbfh, float* __restrict__ rbfh2, int n)
{
    __shared__ float w2[BSZ * HH];
    __shared__ float wr[NRAD * HH];
    const int j = threadIdx.x;
    #pragma unroll
    for (int b = 0; b < BSZ; ++b) w2[b * HH + j] = W_rbf2[b * HH + j];
    #pragma unroll
    for (int r = 0; r < NRAD; ++r) wr[r * HH + j] = W_rbf[r * HH + j];
    __syncthreads();

    const int row0 = blockIdx.x * 32;
    for (int rr = 0; rr < 32; ++rr) {
        const int row = row0 + rr;
        if (row >= n) return;
        const float4* rp = reinterpret_cast<const float4*>(rb8 + (size_t)row * BSZ);
        const float4 ra = __ldg(rp), rb = __ldg(rp + 1);
        float a1 = ra.x * w2[0 * HH + j] + ra.y * w2[1 * HH + j] +
                   ra.z * w2[2 * HH + j] + ra.w * w2[3 * HH + j] +
                   rb.x * w2[4 * HH + j] + rb.y * w2[5 * HH + j] +
                   rb.z * w2[6 * HH + j] + rb.w * w2[7 * HH + j];
        float a2 = 0.f;
        #pragma unroll
        for (int r = 0; r < NRAD; ++r) a2 += __ldg(&rbf[(size_t)row * NRAD + r]) * wr[r * HH + j];
        rbfh[(size_t)row * HH + j]  = a1;
        rbfh2[(size_t)row * HH + j] = a2;
    }
}

// ---------------- T-space: X[T,K] @ W1[K,8] -> out8[T,8] ----------------
template <int K, int PK>
__global__ void proj8_kernel(const float* __restrict__ X, const float* __restrict__ W1,
                             float* __restrict__ out8, int nrows)
{
    __shared__ float wcm[BSZ * PK];
    __shared__ float red[8][32 * 33];
    const int tid = threadIdx.x;
    for (int x = tid; x < BSZ * PK; x += blockDim.x) wcm[x] = 0.f;
    __syncthreads();
    for (int x = tid; x < K * BSZ; x += blockDim.x) {
        const int i = x / BSZ, b = x % BSZ;
        wcm[b * PK + i] = W1[x];
    }
    __syncthreads();

    const int warp = tid >> 5, lane = tid & 31;
    float* myred = &red[warp][0];
    const int nw = blockDim.x >> 5;
    constexpr int ITERS = (K + 31) / 32;

    for (int r0 = (blockIdx.x * nw + warp) * 4; r0 < nrows; r0 += gridDim.x * nw * 4) {
        float acc[4][BSZ] = {};
        const float* x0 = X + (size_t)r0 * K;
        #pragma unroll
        for (int k = 0; k < ITERS; ++k) {
            const int i = lane + k * 32;
            float xv[4] = {0.f, 0.f, 0.f, 0.f};
            if (i < K) {
                #pragma unroll
                for (int rr = 0; rr < 4; ++rr) xv[rr] = x0[(size_t)rr * K + i];
            }
            #pragma unroll
            for (int b = 0; b < BSZ; ++b) {
                const float w = wcm[b * PK + i];
                #pragma unroll
                for (int rr = 0; rr < 4; ++rr) acc[rr][b] += w * xv[rr];
            }
        }
        #pragma unroll
        for (int rr = 0; rr < 4; ++rr)
            #pragma unroll
            for (int b = 0; b < BSZ; ++b)
                myred[lane * 33 + rr * BSZ + b] = acc[rr][b];
        __syncwarp();
        float s = 0.f;
        #pragma unroll
        for (int l = 0; l < 32; ++l) s += myred[l * 33 + lane];
        out8[(size_t)r0 * BSZ + lane] = s;
        __syncwarp();
    }
}

// ---------------- triplet gather/scale/scatter ----------------
__global__ void triplet_kernel(const float* __restrict__ t8, const float* __restrict__ s8,
                               const float* __restrict__ W_t2, const float* __restrict__ W_sbf2,
                               const float* __restrict__ xdown,
                               const int* __restrict__ idx_kj, const int* __restrict__ idx_ji,
                               float* __restrict__ acc, int nt)
{
    __shared__ float wt2s[BSZ * IC];
    __shared__ float ws2s[BSZ * IC];
    const int tid = threadIdx.x;
    for (int i = tid; i < BSZ * IC; i += blockDim.x) { wt2s[i] = W_t2[i]; ws2s[i] = W_sbf2[i]; }
    __syncthreads();

    const int warp = tid >> 5, lane = tid & 31;
    const int total_warps = (blockDim.x * gridDim.x) >> 5;

    for (int tr = blockIdx.x * (blockDim.x >> 5) + warp; tr < nt; tr += total_warps) {
        const float4* tp = reinterpret_cast<const float4*>(t8 + (size_t)tr * BSZ);
        const float4 ta = __ldg(tp), tb = __ldg(tp + 1);
        const float4* sp = reinterpret_cast<const float4*>(s8 + (size_t)tr * BSZ);
        const float4 sa = __ldg(sp), sb = __ldg(sp + 1);
        const float tv[BSZ] = {ta.x, ta.y, ta.z, ta.w, tb.x, tb.y, tb.z, tb.w};
        const float sv[BSZ] = {sa.x, sa.y, sa.z, sa.w, sb.x, sb.y, sb.z, sb.w};
        const int kj = idx_kj[tr], ji = idx_ji[tr];
        const int c0 = lane, c1 = lane + 32;
        float t0 = 0.f, t1 = 0.f, s0 = 0.f, s1 = 0.f;
        #pragma unroll
        for (int b = 0; b < BSZ; ++b) {
            t0 += tv[b] * wt2s[b * IC + c0];
            t1 += tv[b] * wt2s[b * IC + c1];
            s0 += sv[b] * ws2s[b * IC + c0];
            s1 += sv[b] * ws2s[b * IC + c1];
        }
        const float g0 = xdown[(size_t)kj * IC + c0];
        const float g1 = xdown[(size_t)kj * IC + c1];
        atomicAdd(acc + (size_t)ji * IC + c0, g0 * t0 * s0);
        atomicAdd(acc + (size_t)ji * IC + c1, g1 * t1 * s1);
    }
}

__global__ void zero4_kernel(float4* __restrict__ p, int n4)
{
    const int i = blockIdx.x * blockDim.x + threadIdx.x;
    if (i < n4) p[i] = make_float4(0.f, 0.f, 0.f, 0.f);
}

// ---------------- launch ----------------
extern "C" void kernel_launch(void* const* d_in, const int* in_sizes, int n_in,
                              void* d_out, int out_size)
{
    const float* e1     = (const float*)d_in[0];
    const float* rbf    = (const float*)d_in[1];
    const float* sbf    = (const float*)d_in[2];
    const float* tt     = (const float*)d_in[3];
    const int*   idx_kj = (const int*)d_in[4];
    const int*   idx_ji = (const int*)d_in[5];
    const float* W_rbf1 = (const float*)d_in[6];
    const float* W_rbf2 = (const float*)d_in[7];
    const float* W_sbf1 = (const float*)d_in[8];
    const float* W_sbf2 = (const float*)d_in[9];
    const float* W_t1   = (const float*)d_in[10];
    const float* W_t2   = (const float*)d_in[11];
    const float* W_rbf  = (const float*)d_in[12];
    const float* W_kj   = (const float*)d_in[13];
    const float* b_kj   = (const float*)d_in[14];
    const float* W_ji   = (const float*)d_in[15];
    const float* b_ji   = (const float*)d_in[16];
    const float* W_down = (const float*)d_in[17];
    const float* W_up   = (const float*)d_in[18];
    const float* Wb1    = (const float*)d_in[19];
    const float* bb1    = (const float*)d_in[20];
    const float* Wb2    = (const float*)d_in[21];
    const float* bb2    = (const float*)d_in[22];
    const float* W_lin  = (const float*)d_in[23];
    const float* b_lin  = (const float*)d_in[24];
    const float* Wa1    = (const float*)d_in[25];
    const float* ba1    = (const float*)d_in[26];
    const float* Wa2    = (const float*)d_in[27];
    const float* ba2    = (const float*)d_in[28];

    const int E = in_sizes[0] / HH;
    const int T = in_sizes[4];

    float *xji, *rbfh, *rbfh2, *rb8, *xdown, *acc, *t8, *s8, *A, *B, *C;
    cudaGetSymbolAddress((void**)&xji,   g_xji);
    cudaGetSymbolAddress((void**)&rbfh,  g_rbfh);
    cudaGetSymbolAddress((void**)&rbfh2, g_rbfh2);
    cudaGetSymbolAddress((void**)&rb8,   g_rb8);
    cudaGetSymbolAddress((void**)&xdown, g_xdown);
    cudaGetSymbolAddress((void**)&acc,   g_acc);
    cudaGetSymbolAddress((void**)&t8,    g_t8);
    cudaGetSymbolAddress((void**)&s8,    g_s8);
    cudaGetSymbolAddress((void**)&A,     g_bufA);
    cudaGetSymbolAddress((void**)&B,     g_bufB);
    cudaGetSymbolAddress((void**)&C,     g_bufC);

    float* out_e1 = (float*)d_out;
    float* out_e2 = (float*)d_out + (size_t)E * HH;

    const int WS = HH * HH;

    // dynamic smem: As[64][132]*4B + Bs[64][NOUT]*8B
    const int sm_hh = 64 * 132 * 4 + 64 * 128 * 8;   // 99328
    const int sm_dn = 64 * 132 * 4 + 64 * 64 * 8;    // 66560
    const int sm_up = 64 * 132 * 4 + 64 * 128 * 8;   // 99328
    cudaFuncSetAttribute(gemm_f2<HH, HH>, cudaFuncAttributeMaxDynamicSharedMemorySize, sm_hh);
    cudaFuncSetAttribute(gemm_f2<HH, IC>, cudaFuncAttributeMaxDynamicSharedMemorySize, sm_dn);
    cudaFuncSetAttribute(gemm_f2<IC, HH>, cudaFuncAttributeMaxDynamicSharedMemorySize, sm_up);

    const int gblocks = (E + 127) / 128;

    // stream index 3 = profiled launch: gemm_f2<128,128>
    rb8_kernel<<<(E + 255) / 256, 256>>>(rbf, W_rbf1, rb8, E);                       // 0
    rbfh_kernel<<<(E + 31) / 32, HH>>>(rb8, rbf, W_rbf2, W_rbf, rbfh, rbfh2, E);     // 1
    zero4_kernel<<<(E * IC / 4 + 255) / 256, 256>>>((float4*)acc, E * IC / 4);       // 2

    // 3 (profiled): x_ji = silu(e1 @ W_ji + b_ji)
    gemm_f2<HH, HH><<<gblocks, 256, sm_hh>>>(e1, W_ji, b_ji, nullptr, nullptr, xji, nullptr, nullptr, E, 1);
    // A = silu(e1 @ W_kj + b_kj) * rbfh
    gemm_f2<HH, HH><<<gblocks, 256, sm_hh>>>(e1, W_kj, b_kj, rbfh, nullptr, A, nullptr, nullptr, E, 1);
    // xdown = silu(A @ W_down)
    gemm_f2<HH, IC><<<gblocks, 256, sm_dn>>>(A, W_down, nullptr, nullptr, nullptr, xdown, nullptr, nullptr, E, 1);

    // T-space projections
    proj8_kernel<TK, 320><<<2048, 256>>>(tt, W_t1, t8, T);
    proj8_kernel<SBFK, 64><<<2048, 256>>>(sbf, W_sbf1, s8, T);

    // gather * sbf_h * t_h, scatter-add by idx_ji
    triplet_kernel<<<2368, 256>>>(t8, s8, W_t2, W_sbf2, xdown, idx_kj, idx_ji, acc, T);

    // A = silu(acc @ W_up) + x_ji
    gemm_f2<IC, HH><<<gblocks, 256, sm_up>>>(acc, W_up, nullptr, nullptr, xji, A, nullptr, nullptr, E, 1);

    // residual before (1 layer)
    gemm_f2<HH, HH><<<gblocks, 256, sm_hh>>>(A, Wb1, bb1, nullptr, nullptr, B, nullptr, nullptr, E, 1);
    gemm_f2<HH, HH><<<gblocks, 256, sm_hh>>>(B, Wb2, bb2, nullptr, A, C, nullptr, nullptr, E, 1);

    // h = silu(C @ W_lin + b_lin) + e1
    gemm_f2<HH, HH><<<gblocks, 256, sm_hh>>>(C, W_lin, b_lin, nullptr, e1, A, nullptr, nullptr, E, 1);

    // residual after layer 0
    gemm_f2<HH, HH><<<gblocks, 256, sm_hh>>>(A, Wa1, ba1, nullptr, nullptr, B, nullptr, nullptr, E, 1);
    gemm_f2<HH, HH><<<gblocks, 256, sm_hh>>>(B, Wa2, ba2, nullptr, A, C, nullptr, nullptr, E, 1);
    // residual after layer 1 -> final outputs (e1_out, e2_out = e1_out * rbfh2)
    gemm_f2<HH, HH><<<gblocks, 256, sm_hh>>>(C, Wa1 + WS, ba1 + HH, nullptr, nullptr, B, nullptr, nullptr, E, 1);
    gemm_f2<HH, HH><<<gblocks, 256, sm_hh>>>(B, Wa2 + WS, ba2 + HH, nullptr, C, out_e1, rbfh2, out_e2, E, 1);
}